// round 14
// baseline (speedup 1.0000x reference)
#include <cuda_runtime.h>
#include <cuda_bf16.h>
#include <cstdint>

// ---------------------------------------------------------------------------
// LSTMPointerNet: BS=16, NMEM=256, NQ=63 (T=64), D=512, H=512
// Output: score [16,64,256] f32
//
// R14 (= R13 fixed): LSTM step dot with 4x4 register tiling (4 gate-rows x
// 4 batches x 32-k chunk per thread). Per-SM operand traffic 1MB -> 256KB;
// no smem staging; smem only for the 16-way k-chunk reduction (packed f32x2
// adds, fixed order). g_h relaid to [b][k]. PDL trigger after h/c stores.
// ---------------------------------------------------------------------------

__device__ float g_xcat[1024 * 512];    // [t*16+b][d]
__device__ float g_wihT[512 * 2048];    // w_ih^T  [d][4H]
__device__ float g_xg  [1024 * 2048];   // [t*16+b][4H]  x @ w_ih^T (no bias)
__device__ float g_feat[4096 * 512];    // [b*256+m][h]
__device__ float g_ys  [1024 * 512];    // [b*64+t][h]
__device__ float g_q   [1024 * 512];    // [b*64+t][h]
__device__ float g_h   [2 * 16 * 512];  // double-buffered h, [buf][b][k]
__device__ float g_c   [512 * 16];      // cell state, [k][b]

// ---------------- helpers ---------------------------------------------------

__device__ __forceinline__ void fma2(unsigned long long& d,
                                     unsigned long long a,
                                     unsigned long long b) {
    asm("fma.rn.f32x2 %0, %1, %2, %0;" : "+l"(d) : "l"(a), "l"(b));
}
__device__ __forceinline__ unsigned long long add2(unsigned long long a,
                                                   unsigned long long b) {
    unsigned long long r;
    asm("add.rn.f32x2 %0, %1, %2;" : "=l"(r) : "l"(a), "l"(b));
    return r;
}
__device__ __forceinline__ unsigned long long pk2(float x) {
    unsigned long long r;
    asm("mov.b64 %0, {%1, %1};" : "=l"(r) : "f"(x));
    return r;
}
__device__ __forceinline__ void unpk(unsigned long long v, float& lo, float& hi) {
    asm("mov.b64 {%0, %1}, %2;" : "=f"(lo), "=f"(hi) : "l"(v));
}
__device__ __forceinline__ float upsum(unsigned long long v) {
    float lo, hi; unpk(v, lo, hi); return lo + hi;
}
__device__ __forceinline__ float rcp_approx(float x) {
    float r;
    asm("rcp.approx.f32 %0, %1;" : "=f"(r) : "f"(x));
    return r;
}

// rational poly tanh: 1 MUFU (rcp) + ~11 FMA; abs err ~1e-6
__device__ __forceinline__ float tanh_poly(float x) {
    const float kClamp = 7.90531110763549805f;
    float xc = fminf(fmaxf(x, -kClamp), kClamp);
    float x2 = xc * xc;
    float p = fmaf(x2, -2.76076847742355e-16f, 2.00018790482477e-13f);
    p = fmaf(x2, p, -8.60467152213735e-11f);
    p = fmaf(x2, p, 5.12229709037114e-08f);
    p = fmaf(x2, p, 1.48572235717979e-05f);
    p = fmaf(x2, p, 6.37261928875436e-04f);
    p = fmaf(x2, p, 4.89352455891786e-03f);
    p *= xc;
    float q = fmaf(x2, 1.19825839466702e-06f, 1.18534705686654e-04f);
    q = fmaf(x2, q, 2.26843463243900e-03f);
    q = fmaf(x2, q, 4.89352518554385e-03f);
    return p * rcp_approx(q);
}
__device__ __forceinline__ float sigm_poly(float x) {
    return fmaf(0.5f, tanh_poly(0.5f * x), 0.5f);
}

// ---------------- pack x = concat(init_i, lstm_in), seq-first ---------------

__global__ __launch_bounds__(256) void pack_x_kernel(const float* __restrict__ lstm_in,
                                                     const float* __restrict__ init_i) {
    int gid  = blockIdx.x * 256 + threadIdx.x;   // 131072 float4s
    int fidx = gid * 4;
    int row  = fidx >> 9;        // t*16 + b
    int d    = fidx & 511;
    int t = row >> 4, b = row & 15;
    float4 v;
    if (t == 0) v = *(const float4*)&init_i[d];
    else        v = *(const float4*)&lstm_in[(size_t)(b * 63 + (t - 1)) * 512 + d];
    *(float4*)&g_xcat[fidx] = v;
}

// ---------------- transpose w_ih [2048,512] -> w_ihT [512,2048] --------------

__global__ __launch_bounds__(256) void transpose_kernel(const float* __restrict__ in) {
    __shared__ float tile[32][33];
    int rb = blockIdx.y * 32;
    int cb = blockIdx.x * 32;
    int tx = threadIdx.x & 31, ty = threadIdx.x >> 5;   // 32 x 8
#pragma unroll
    for (int i = 0; i < 4; i++)
        tile[ty + i * 8][tx] = in[(size_t)(rb + ty + i * 8) * 512 + cb + tx];
    __syncthreads();
#pragma unroll
    for (int i = 0; i < 4; i++)
        g_wihT[(size_t)(cb + ty + i * 8) * 2048 + rb + tx] = tile[tx][ty + i * 8];
}

// ---------------- init h ([b][k] layout), c ([k][b]) -------------------------

__global__ __launch_bounds__(256) void init_hc_kernel(const float* __restrict__ init_h,
                                                      const float* __restrict__ init_c) {
    int gid = blockIdx.x * 256 + threadIdx.x;   // 8192 entries
    int k = gid >> 4, b = gid & 15;
    g_h[b * 512 + k] = init_h[k];
    g_c[k * 16 + b]  = init_c[k];
}

// ---------------- f32x2 GEMM, register double-buffered -----------------------
// C[M,N] = A[M,K] @ B[K,N]. 128 threads, tile 128x64, 8x8/thread.

__global__ __launch_bounds__(128) void gemm_f32x2(const float* __restrict__ A,
                                                  const float* __restrict__ B,
                                                  float* __restrict__ C,
                                                  int M, int N, int K) {
    __shared__ float As[16][132];
    __shared__ float Bs[16][64];
    const int tid = threadIdx.x;
    const int tx = tid & 7;
    const int ty = tid >> 3;
    const int m0 = blockIdx.y * 128, n0 = blockIdx.x * 64;

    cudaGridDependencySynchronize();

    unsigned long long acc[8][4];
#pragma unroll
    for (int i = 0; i < 8; i++)
#pragma unroll
        for (int p = 0; p < 4; p++) acc[i][p] = 0ull;

    float4 ra[4], rb[2];
#pragma unroll
    for (int l = 0; l < 4; l++) {
        int e = tid + l * 128;
        int row = e >> 2, kq = e & 3;
        ra[l] = *(const float4*)&A[(size_t)(m0 + row) * K + kq * 4];
    }
#pragma unroll
    for (int l = 0; l < 2; l++) {
        int e = tid + l * 128;
        int kr = e >> 4, nq = e & 15;
        rb[l] = *(const float4*)&B[(size_t)kr * N + n0 + nq * 4];
    }

    for (int k0 = 0; k0 < K; k0 += 16) {
#pragma unroll
        for (int l = 0; l < 4; l++) {
            int e = tid + l * 128;
            int row = e >> 2, kq = e & 3;
            As[kq * 4 + 0][row] = ra[l].x;
            As[kq * 4 + 1][row] = ra[l].y;
            As[kq * 4 + 2][row] = ra[l].z;
            As[kq * 4 + 3][row] = ra[l].w;
        }
#pragma unroll
        for (int l = 0; l < 2; l++) {
            int e = tid + l * 128;
            int kr = e >> 4, nq = e & 15;
            *(float4*)&Bs[kr][nq * 4] = rb[l];
        }
        __syncthreads();
        if (k0 + 16 < K) {
#pragma unroll
            for (int l = 0; l < 4; l++) {
                int e = tid + l * 128;
                int row = e >> 2, kq = e & 3;
                ra[l] = *(const float4*)&A[(size_t)(m0 + row) * K + k0 + 16 + kq * 4];
            }
#pragma unroll
            for (int l = 0; l < 2; l++) {
                int e = tid + l * 128;
                int kr = e >> 4, nq = e & 15;
                rb[l] = *(const float4*)&B[(size_t)(k0 + 16 + kr) * N + n0 + nq * 4];
            }
        }
#pragma unroll
        for (int k = 0; k < 16; k++) {
            float4 a0 = *(const float4*)&As[k][ty * 8];
            float4 a1 = *(const float4*)&As[k][ty * 8 + 4];
            ulonglong2 blo = *(const ulonglong2*)&Bs[k][tx * 4];
            ulonglong2 bhi = *(const ulonglong2*)&Bs[k][32 + tx * 4];
            float am[8] = {a0.x, a0.y, a0.z, a0.w, a1.x, a1.y, a1.z, a1.w};
#pragma unroll
            for (int i = 0; i < 8; i++) {
                unsigned long long pa = pk2(am[i]);
                fma2(acc[i][0], pa, blo.x);
                fma2(acc[i][1], pa, blo.y);
                fma2(acc[i][2], pa, bhi.x);
                fma2(acc[i][3], pa, bhi.y);
            }
        }
        __syncthreads();
    }
#pragma unroll
    for (int i = 0; i < 8; i++) {
        float* crow = C + (size_t)(m0 + ty * 8 + i) * N;
#pragma unroll
        for (int g = 0; g < 2; g++) {
#pragma unroll
            for (int p = 0; p < 2; p++) {
                int n = n0 + g * 32 + tx * 4 + p * 2;
                float lo, hi;
                unpk(acc[i][g * 2 + p], lo, hi);
                crow[n]     = lo;
                crow[n + 1] = hi;
            }
        }
    }
    // trigger AFTER stores: downstream may read C immediately
    cudaTriggerProgrammaticLaunchCompletion();
}

// ---------------- LSTM single step (launch per t) ----------------------------
// 128 blocks x 256 threads; block owns h-indices hb..hb+3 (16 gate rows =
// 4 gates x 4 offsets). Thread = (rg=gate, bg, kc): 4 rows x 4 batches x
// 32-k chunk, 4x4 f32x2 register tile. Operands straight from L1/L2.
// kc-reduction through smem with packed f32x2 adds (fixed order).

__global__ __launch_bounds__(256) void lstm_step_kernel(int t,
                                                        const float* __restrict__ w_hh,
                                                        const float* __restrict__ b_ih,
                                                        const float* __restrict__ b_hh) {
    __shared__ unsigned long long red[16 * 273];  // [kc][lr*17 + b]
    __shared__ float gsm[16][17];                 // [lr = gate*4+off][b]

    const int tid = threadIdx.x;
    const int hb  = blockIdx.x * 4;
    const int rg  = tid >> 6;          // gate 0..3 (warp-uniform)
    const int bg  = (tid >> 4) & 3;    // batch group 0..3
    const int kc  = tid & 15;          // k-chunk 0..15 (32 k each)
    const int k0  = kc * 32;

    // prelude: phase-2 operands (independent of previous step).
    // thread handles reduction slots tid and tid+128 -> (lr, b) pairs:
    const int lr0 = tid >> 4, bb0 = tid & 15;              // tid in 0..255 -> lr 0..15
    const int lr1 = (tid + 128 < 256 ? tid + 128 : tid - 128) >> 4;
    const int bb1 = tid & 15;
    // Use disjoint halves: threads 0..127 reduce slots (lr0,b), threads
    // 128..255 reduce (lr0,b) too via lr0 covering 8..15. Simpler: each
    // thread reduces exactly ONE slot (256 slots = 16 lr x 16 b).
    const int gw0 = (lr0 >> 2) * 512 + hb + (lr0 & 3);
    const float xg0 = g_xg[t * 32768 + bb0 * 2048 + gw0];
    const float bs0 = b_ih[gw0] + b_hh[gw0];
    (void)lr1; (void)bb1;

    // w row pointers: warp rg covers gate rg, rows hb..hb+3
    const float* wp0 = w_hh + (size_t)(rg * 512 + hb + 0) * 512;
    const float* wp1 = w_hh + (size_t)(rg * 512 + hb + 1) * 512;
    const float* wp2 = w_hh + (size_t)(rg * 512 + hb + 2) * 512;
    const float* wp3 = w_hh + (size_t)(rg * 512 + hb + 3) * 512;

    cudaGridDependencySynchronize();

    const float* hbuf = g_h + (t & 1) * 8192;   // [b][k]
    const float* hp0 = hbuf + (bg * 4 + 0) * 512;
    const float* hp1 = hbuf + (bg * 4 + 1) * 512;
    const float* hp2 = hbuf + (bg * 4 + 2) * 512;
    const float* hp3 = hbuf + (bg * 4 + 3) * 512;

    unsigned long long acc[4][4];
#pragma unroll
    for (int i = 0; i < 4; i++)
#pragma unroll
        for (int j = 0; j < 4; j++) acc[i][j] = 0ull;

#pragma unroll
    for (int q = 0; q < 8; q++) {
        const int kk = k0 + q * 4;
        ulonglong2 wv[4], hv[4];
        wv[0] = *(const ulonglong2*)(wp0 + kk);
        wv[1] = *(const ulonglong2*)(wp1 + kk);
        wv[2] = *(const ulonglong2*)(wp2 + kk);
        wv[3] = *(const ulonglong2*)(wp3 + kk);
        hv[0] = *(const ulonglong2*)(hp0 + kk);
        hv[1] = *(const ulonglong2*)(hp1 + kk);
        hv[2] = *(const ulonglong2*)(hp2 + kk);
        hv[3] = *(const ulonglong2*)(hp3 + kk);
#pragma unroll
        for (int i = 0; i < 4; i++)
#pragma unroll
            for (int j = 0; j < 4; j++) {
                fma2(acc[i][j], wv[i].x, hv[j].x);
                fma2(acc[i][j], wv[i].y, hv[j].y);
            }
    }

    // stash per-(row,b) partials: red[kc][lr*17 + b]
#pragma unroll
    for (int i = 0; i < 4; i++) {
        const int lr = rg * 4 + i;
        const int base = kc * 273 + lr * 17 + bg * 4;
#pragma unroll
        for (int j = 0; j < 4; j++) red[base + j] = acc[i][j];
    }
    __syncthreads();

    // phase 2: each thread reduces one (lr, b) slot over 16 k-chunks
    {
        const int a0 = lr0 * 17 + bb0;
        unsigned long long s = red[a0];
#pragma unroll
        for (int c = 1; c < 16; c++) s = add2(s, red[c * 273 + a0]);
        gsm[lr0][bb0] = (xg0 + upsum(s)) + bs0;
    }
    __syncthreads();

    // phase 3: cell update (validated tail math)
    // gsm[lr][b], lr = gate*4 + off; gate g row jj at lr = g*4 + jj
    if (tid < 64) {
        int jj = tid >> 4, bb = tid & 15;
        float gi = sigm_poly(gsm[0 * 4 + jj][bb]);   // i
        float gf = sigm_poly(gsm[1 * 4 + jj][bb]);   // f
        float gg = tanh_poly(gsm[2 * 4 + jj][bb]);   // g
        float go = sigm_poly(gsm[3 * 4 + jj][bb]);   // o
        int ci = (hb + jj) * 16 + bb;
        float c = gf * g_c[ci] + gi * gg;
        g_c[ci] = c;
        float h = go * tanh_poly(c);
        g_h[((t + 1) & 1) * 8192 + bb * 512 + hb + jj] = h;
        g_ys[(size_t)((bb << 6) + t) * 512 + hb + jj] = h;
    }
    __syncthreads();
    __threadfence();
    // trigger AFTER h/c stores: next step may read them once all blocks fire
    cudaTriggerProgrammaticLaunchCompletion();
}

// ---------------- score: out[b][t][m] = sum_h tanh(feat+q) * v --------------

__global__ __launch_bounds__(128) void score_kernel(const float* __restrict__ v,
                                                    float* __restrict__ out) {
    cudaGridDependencySynchronize();
    const int b  = blockIdx.y, mg = blockIdx.x;
    const int w  = threadIdx.x >> 5, lane = threadIdx.x & 31;
    const int m  = mg * 4 + w;
    const float* fp = g_feat + (size_t)((b << 8) + m) * 512;

    float4 ff[4], vv[4];
#pragma unroll
    for (int j = 0; j < 4; j++) {
        ff[j] = *(const float4*)&fp[lane * 4 + j * 128];
        vv[j] = *(const float4*)&v[lane * 4 + j * 128];
    }
    for (int t = 0; t < 64; t++) {
        const float* qp = g_q + (size_t)((b << 6) + t) * 512;
        float s = 0.0f;
#pragma unroll
        for (int j = 0; j < 4; j++) {
            float4 qv = __ldg((const float4*)&qp[lane * 4 + j * 128]);
            s += tanh_poly(ff[j].x + qv.x) * vv[j].x;
            s += tanh_poly(ff[j].y + qv.y) * vv[j].y;
            s += tanh_poly(ff[j].z + qv.z) * vv[j].z;
            s += tanh_poly(ff[j].w + qv.w) * vv[j].w;
        }
#pragma unroll
        for (int off = 16; off; off >>= 1)
            s += __shfl_xor_sync(0xffffffffu, s, off);
        if (lane == 0) out[(size_t)((b << 6) + t) * 256 + m] = s;
    }
}

// ---------------- PDL launch helper -----------------------------------------

template <typename F, typename... Args>
static inline void launch_pdl(F f, dim3 grid, dim3 block, Args... args) {
    cudaLaunchConfig_t cfg = {};
    cfg.gridDim = grid;
    cfg.blockDim = block;
    cfg.dynamicSmemBytes = 0;
    cfg.stream = 0;
    cudaLaunchAttribute attr[1];
    attr[0].id = cudaLaunchAttributeProgrammaticStreamSerialization;
    attr[0].val.programmaticStreamSerializationAllowed = 1;
    cfg.attrs = attr;
    cfg.numAttrs = 1;
    cudaLaunchKernelEx(&cfg, f, args...);
}

// ---------------- launch ----------------------------------------------------

extern "C" void kernel_launch(void* const* d_in, const int* in_sizes, int n_in,
                              void* d_out, int out_size) {
    const int o = (n_in == 12) ? 1 : 0;
    const float* ks      = (const float*)d_in[0];
    const float* lstm_in = (const float*)d_in[2 - o];
    const float* init_h  = (const float*)d_in[3 - o];
    const float* init_c  = (const float*)d_in[4 - o];
    const float* init_i  = (const float*)d_in[5 - o];
    const float* w_ih    = (const float*)d_in[6 - o];
    const float* w_hh    = (const float*)d_in[7 - o];
    const float* b_ih    = (const float*)d_in[8 - o];
    const float* b_hh    = (const float*)d_in[9 - o];
    const float* attn_wm = (const float*)d_in[10 - o];
    const float* attn_wq = (const float*)d_in[11 - o];
    const float* attn_v  = (const float*)d_in[12 - o];
    float* out = (float*)d_out;

    void *p_xcat, *p_wihT, *p_xg, *p_feat, *p_ys, *p_q;
    cudaGetSymbolAddress(&p_xcat, g_xcat);
    cudaGetSymbolAddress(&p_wihT, g_wihT);
    cudaGetSymbolAddress(&p_xg,   g_xg);
    cudaGetSymbolAddress(&p_feat, g_feat);
    cudaGetSymbolAddress(&p_ys,   g_ys);
    cudaGetSymbolAddress(&p_q,    g_q);

    // 1) prep
    pack_x_kernel<<<512, 256>>>(lstm_in, init_i);
    transpose_kernel<<<dim3(512 / 32, 2048 / 32), 256>>>(w_ih);
    init_hc_kernel<<<32, 256>>>(init_h, init_c);

    // 2) xg = x @ w_ihT   [1024 x 2048]
    launch_pdl(gemm_f32x2, dim3(2048 / 64, 1024 / 128), dim3(128),
               (const float*)p_xcat, (const float*)p_wihT, (float*)p_xg,
               1024, 2048, 512);

    // 3) feat = knowledge_state @ attn_wm  [4096 x 512]
    launch_pdl(gemm_f32x2, dim3(512 / 64, 4096 / 128), dim3(128),
               ks, attn_wm, (float*)p_feat, 4096, 512, 512);

    // 4) LSTM: 64 step launches (PDL-chained)
    for (int t = 0; t < 64; t++)
        launch_pdl(lstm_step_kernel, dim3(128), dim3(256), t, w_hh, b_ih, b_hh);

    // 5) q = ys @ attn_wq  [1024 x 512]
    launch_pdl(gemm_f32x2, dim3(512 / 64, 1024 / 128), dim3(128),
               (const float*)p_ys, attn_wq, (float*)p_q, 1024, 512, 512);

    // 6) score
    launch_pdl(score_kernel, dim3(64, 16), dim3(128), attn_v, out);
}

// round 15
// speedup vs baseline: 1.6601x; 1.6601x over previous
#include <cuda_runtime.h>
#include <cuda_bf16.h>
#include <cstdint>

// ---------------------------------------------------------------------------
// LSTMPointerNet: BS=16, NMEM=256, NQ=63 (T=64), D=512, H=512
// Output: score [16,64,256] f32
//
// R15: revert LSTM to the R12 step kernel (fastest validated, 7.8us/step).
// New: (a) xg-GEMM and feat-GEMM merged into ONE 512-block launch (they are
// independent; doubles blocks/SM for the latency-bound GEMM), (b) score uses
// tanh_fast (2 MUFU, validated in R9) with 2 m-rows per warp to halve q
// traffic.
// ---------------------------------------------------------------------------

__device__ float g_xcat[1024 * 512];    // [t*16+b][d]
__device__ float g_wihT[512 * 2048];    // w_ih^T  [d][4H]
__device__ float g_xg  [1024 * 2048];   // [t*16+b][4H]  x @ w_ih^T (no bias)
__device__ float g_feat[4096 * 512];    // [b*256+m][h]
__device__ float g_ys  [1024 * 512];    // [b*64+t][h]
__device__ float g_q   [1024 * 512];    // [b*64+t][h]
__device__ float g_h   [2 * 512 * 16];  // double-buffered h, [buf][k][b]
__device__ float g_c   [512 * 16];      // cell state, [k][b]

// ---------------- helpers ---------------------------------------------------

__device__ __forceinline__ void fma2(unsigned long long& d,
                                     unsigned long long a,
                                     unsigned long long b) {
    asm("fma.rn.f32x2 %0, %1, %2, %0;" : "+l"(d) : "l"(a), "l"(b));
}
__device__ __forceinline__ unsigned long long pk2(float x) {
    unsigned long long r;
    asm("mov.b64 %0, {%1, %1};" : "=l"(r) : "f"(x));
    return r;
}
__device__ __forceinline__ void unpk(unsigned long long v, float& lo, float& hi) {
    asm("mov.b64 {%0, %1}, %2;" : "=f"(lo), "=f"(hi) : "l"(v));
}
__device__ __forceinline__ float upsum(unsigned long long v) {
    float lo, hi; unpk(v, lo, hi); return lo + hi;
}
__device__ __forceinline__ float4 ldcg4(const float* p) {
    float4 v;
    asm volatile("ld.global.cg.v4.f32 {%0,%1,%2,%3}, [%4];"
                 : "=f"(v.x), "=f"(v.y), "=f"(v.z), "=f"(v.w) : "l"(p));
    return v;
}
__device__ __forceinline__ float rcp_approx(float x) {
    float r;
    asm("rcp.approx.f32 %0, %1;" : "=f"(r) : "f"(x));
    return r;
}

// fast tanh: 1 - 2/(exp2(2x*log2e)+1); 2 MUFU; ~1e-6 abs err (R9-validated)
__device__ __forceinline__ float tanh_fast(float x) {
    float e, r;
    asm("ex2.approx.f32 %0, %1;" : "=f"(e) : "f"(x * 2.8853900817779268f));
    asm("rcp.approx.f32 %0, %1;" : "=f"(r) : "f"(e + 1.0f));
    return fmaf(-2.0f, r, 1.0f);
}

// rational poly tanh (cell tail only; R12-validated)
__device__ __forceinline__ float tanh_poly(float x) {
    const float kClamp = 7.90531110763549805f;
    float xc = fminf(fmaxf(x, -kClamp), kClamp);
    float x2 = xc * xc;
    float p = fmaf(x2, -2.76076847742355e-16f, 2.00018790482477e-13f);
    p = fmaf(x2, p, -8.60467152213735e-11f);
    p = fmaf(x2, p, 5.12229709037114e-08f);
    p = fmaf(x2, p, 1.48572235717979e-05f);
    p = fmaf(x2, p, 6.37261928875436e-04f);
    p = fmaf(x2, p, 4.89352455891786e-03f);
    p *= xc;
    float q = fmaf(x2, 1.19825839466702e-06f, 1.18534705686654e-04f);
    q = fmaf(x2, q, 2.26843463243900e-03f);
    q = fmaf(x2, q, 4.89352518554385e-03f);
    return p * rcp_approx(q);
}
__device__ __forceinline__ float sigm_poly(float x) {
    return fmaf(0.5f, tanh_poly(0.5f * x), 0.5f);
}

// ---------------- pack x = concat(init_i, lstm_in), seq-first ---------------

__global__ __launch_bounds__(256) void pack_x_kernel(const float* __restrict__ lstm_in,
                                                     const float* __restrict__ init_i) {
    int gid  = blockIdx.x * 256 + threadIdx.x;   // 131072 float4s
    int fidx = gid * 4;
    int row  = fidx >> 9;        // t*16 + b
    int d    = fidx & 511;
    int t = row >> 4, b = row & 15;
    float4 v;
    if (t == 0) v = *(const float4*)&init_i[d];
    else        v = *(const float4*)&lstm_in[(size_t)(b * 63 + (t - 1)) * 512 + d];
    *(float4*)&g_xcat[fidx] = v;
}

// ---------------- transpose w_ih [2048,512] -> w_ihT [512,2048] --------------

__global__ __launch_bounds__(256) void transpose_kernel(const float* __restrict__ in) {
    __shared__ float tile[32][33];
    int rb = blockIdx.y * 32;
    int cb = blockIdx.x * 32;
    int tx = threadIdx.x & 31, ty = threadIdx.x >> 5;   // 32 x 8
#pragma unroll
    for (int i = 0; i < 4; i++)
        tile[ty + i * 8][tx] = in[(size_t)(rb + ty + i * 8) * 512 + cb + tx];
    __syncthreads();
#pragma unroll
    for (int i = 0; i < 4; i++)
        g_wihT[(size_t)(cb + ty + i * 8) * 2048 + rb + tx] = tile[tx][ty + i * 8];
}

// ---------------- init h, c ([k][b] layouts) ---------------------------------

__global__ __launch_bounds__(256) void init_hc_kernel(const float* __restrict__ init_h,
                                                      const float* __restrict__ init_c) {
    int gid = blockIdx.x * 256 + threadIdx.x;   // 8192 entries
    int k = gid >> 4, b = gid & 15;
    g_h[k * 16 + b] = init_h[k];
    g_c[k * 16 + b] = init_c[k];
}

// ---------------- f32x2 GEMM body (register double-buffered) -----------------
// C[M,N] = A[M,K] @ B[K,N]. 128 threads, tile 128x64, 8x8/thread.

__device__ __forceinline__ void gemm_body(const float* __restrict__ A,
                                          const float* __restrict__ B,
                                          float* __restrict__ C,
                                          int N, int K, int m0, int n0,
                                          float (*As)[132], float (*Bs)[64]) {
    const int tid = threadIdx.x;
    const int tx = tid & 7;
    const int ty = tid >> 3;

    unsigned long long acc[8][4];
#pragma unroll
    for (int i = 0; i < 8; i++)
#pragma unroll
        for (int p = 0; p < 4; p++) acc[i][p] = 0ull;

    float4 ra[4], rb[2];
#pragma unroll
    for (int l = 0; l < 4; l++) {
        int e = tid + l * 128;
        int row = e >> 2, kq = e & 3;
        ra[l] = *(const float4*)&A[(size_t)(m0 + row) * K + kq * 4];
    }
#pragma unroll
    for (int l = 0; l < 2; l++) {
        int e = tid + l * 128;
        int kr = e >> 4, nq = e & 15;
        rb[l] = *(const float4*)&B[(size_t)kr * N + n0 + nq * 4];
    }

    for (int k0 = 0; k0 < K; k0 += 16) {
#pragma unroll
        for (int l = 0; l < 4; l++) {
            int e = tid + l * 128;
            int row = e >> 2, kq = e & 3;
            As[kq * 4 + 0][row] = ra[l].x;
            As[kq * 4 + 1][row] = ra[l].y;
            As[kq * 4 + 2][row] = ra[l].z;
            As[kq * 4 + 3][row] = ra[l].w;
        }
#pragma unroll
        for (int l = 0; l < 2; l++) {
            int e = tid + l * 128;
            int kr = e >> 4, nq = e & 15;
            *(float4*)&Bs[kr][nq * 4] = rb[l];
        }
        __syncthreads();
        if (k0 + 16 < K) {
#pragma unroll
            for (int l = 0; l < 4; l++) {
                int e = tid + l * 128;
                int row = e >> 2, kq = e & 3;
                ra[l] = *(const float4*)&A[(size_t)(m0 + row) * K + k0 + 16 + kq * 4];
            }
#pragma unroll
            for (int l = 0; l < 2; l++) {
                int e = tid + l * 128;
                int kr = e >> 4, nq = e & 15;
                rb[l] = *(const float4*)&B[(size_t)(k0 + 16 + kr) * N + n0 + nq * 4];
            }
        }
#pragma unroll
        for (int k = 0; k < 16; k++) {
            float4 a0 = *(const float4*)&As[k][ty * 8];
            float4 a1 = *(const float4*)&As[k][ty * 8 + 4];
            ulonglong2 blo = *(const ulonglong2*)&Bs[k][tx * 4];
            ulonglong2 bhi = *(const ulonglong2*)&Bs[k][32 + tx * 4];
            float am[8] = {a0.x, a0.y, a0.z, a0.w, a1.x, a1.y, a1.z, a1.w};
#pragma unroll
            for (int i = 0; i < 8; i++) {
                unsigned long long pa = pk2(am[i]);
                fma2(acc[i][0], pa, blo.x);
                fma2(acc[i][1], pa, blo.y);
                fma2(acc[i][2], pa, bhi.x);
                fma2(acc[i][3], pa, bhi.y);
            }
        }
        __syncthreads();
    }
#pragma unroll
    for (int i = 0; i < 8; i++) {
        float* crow = C + (size_t)(m0 + ty * 8 + i) * N;
#pragma unroll
        for (int g = 0; g < 2; g++) {
#pragma unroll
            for (int p = 0; p < 2; p++) {
                int n = n0 + g * 32 + tx * 4 + p * 2;
                float lo, hi;
                unpk(acc[i][g * 2 + p], lo, hi);
                crow[n]     = lo;
                crow[n + 1] = hi;
            }
        }
    }
}

// merged launch: blocks 0..255 -> xg (1024x2048x512), 256..511 -> feat
// (4096x512x512). Doubles resident blocks/SM for the latency-bound GEMM.
__global__ __launch_bounds__(128) void gemm_merged_kernel(const float* __restrict__ xcat,
                                                          const float* __restrict__ wihT,
                                                          float* __restrict__ xg,
                                                          const float* __restrict__ ks,
                                                          const float* __restrict__ wm,
                                                          float* __restrict__ feat) {
    __shared__ float As[16][132];
    __shared__ float Bs[16][64];
    cudaGridDependencySynchronize();
    const int bid = blockIdx.x;
    if (bid < 256) {
        int bx = bid & 31, by = bid >> 5;     // nx=32, ny=8
        gemm_body(xcat, wihT, xg, 2048, 512, by * 128, bx * 64, As, Bs);
    } else {
        int id = bid - 256;
        int bx = id & 7, by = id >> 3;        // nx=8, ny=32
        gemm_body(ks, wm, feat, 512, 512, by * 128, bx * 64, As, Bs);
    }
    cudaTriggerProgrammaticLaunchCompletion();
}

// single-problem GEMM (q = ys @ wq)
__global__ __launch_bounds__(128) void gemm_single_kernel(const float* __restrict__ A,
                                                          const float* __restrict__ B,
                                                          float* __restrict__ C,
                                                          int N, int K) {
    __shared__ float As[16][132];
    __shared__ float Bs[16][64];
    cudaGridDependencySynchronize();
    gemm_body(A, B, C, N, K, blockIdx.y * 128, blockIdx.x * 64, As, Bs);
    cudaTriggerProgrammaticLaunchCompletion();
}

// ---------------- LSTM single step (exact R12 kernel) ------------------------
// 128 blocks x 256 threads; block owns h-indices hb..hb+3 (16 gate rows).
// thread = (batch b = tid&15, local row r = tid>>4). w slice (32KB) and h
// (32KB) cooperatively staged into dynamic smem (coalesced LDG.cg); dot is
// LDS/FFMA2-bound; trigger after staging.

extern __shared__ float s_dyn[];   // [0:16*516) hs | [16*516:2*16*516) ws

__global__ __launch_bounds__(256) void lstm_step_kernel(int t,
                                                        const float* __restrict__ w_hh,
                                                        const float* __restrict__ b_ih,
                                                        const float* __restrict__ b_hh) {
    __shared__ float gsm[16][17];   // [local gate row][b]
    float* hs = s_dyn;              // [b][k], stride 516
    float* ws = s_dyn + 16 * 516;   // [r][k], stride 516

    const int tid = threadIdx.x;
    const int hb  = blockIdx.x * 4;
    const int b   = tid & 15;
    const int r   = tid >> 4;                    // 0..15
    const int grow = (r >> 2) * 512 + hb + (r & 3);

    // prelude (inputs independent of the previous step)
    const float xg = g_xg[t * 32768 + b * 2048 + grow];
    const float bs = b_ih[grow] + b_hh[grow];
    int widx[8], wrow[8];
#pragma unroll
    for (int i = 0; i < 8; i++) {
        int e = tid + i * 256;          // 0..2047 float4s
        wrow[i] = e >> 7;               // local row 0..15
        widx[i] = e & 127;              // float4 within row
    }

    cudaGridDependencySynchronize();

    // stage h (L2-coherent) and w (coalesced) into smem
    const float* hp = g_h + (t & 1) * 8192;
#pragma unroll
    for (int i = 0; i < 8; i++) {
        int idx = tid + i * 256;        // 2048 float4s
        int k = idx >> 2, bq = (idx & 3) * 4;
        float4 v = ldcg4(hp + idx * 4);
        hs[(bq + 0) * 516 + k] = v.x;
        hs[(bq + 1) * 516 + k] = v.y;
        hs[(bq + 2) * 516 + k] = v.z;
        hs[(bq + 3) * 516 + k] = v.w;
    }
#pragma unroll
    for (int i = 0; i < 8; i++) {
        int lr = wrow[i];
        int gr = (lr >> 2) * 512 + hb + (lr & 3);
        float4 v = ldcg4(&w_hh[(size_t)gr * 512 + widx[i] * 4]);
        *(float4*)&ws[lr * 516 + widx[i] * 4] = v;
    }
    __syncthreads();

    cudaTriggerProgrammaticLaunchCompletion();

    // f32x2 dot, 4 accumulator chains, all-smem operands
    const float* hrow = hs + b * 516;
    const float* wrw  = ws + r * 516;
    unsigned long long a0 = 0, a1 = 0, a2 = 0, a3 = 0;
#pragma unroll 8
    for (int k = 0; k < 512; k += 8) {
        ulonglong2 h0 = *(const ulonglong2*)(hrow + k);
        ulonglong2 h1 = *(const ulonglong2*)(hrow + k + 4);
        ulonglong2 w0 = *(const ulonglong2*)(wrw + k);
        ulonglong2 w1 = *(const ulonglong2*)(wrw + k + 4);
        fma2(a0, h0.x, w0.x);
        fma2(a1, h0.y, w0.y);
        fma2(a2, h1.x, w1.x);
        fma2(a3, h1.y, w1.y);
    }
    gsm[r][b] = (xg + (upsum(a0) + upsum(a1) + upsum(a2) + upsum(a3))) + bs;
    __syncthreads();

    if (tid < 64) {
        int jj = tid >> 4, bb = tid & 15;
        float gi = sigm_poly(gsm[jj][bb]);        // gate i
        float gf = sigm_poly(gsm[4 + jj][bb]);    // gate f
        float gg = tanh_poly(gsm[8 + jj][bb]);    // gate g
        float go = sigm_poly(gsm[12 + jj][bb]);   // gate o
        int ci = (hb + jj) * 16 + bb;
        float c = gf * g_c[ci] + gi * gg;
        g_c[ci] = c;
        float h = go * tanh_poly(c);
        g_h[((t + 1) & 1) * 8192 + ci] = h;
        g_ys[(size_t)((bb << 6) + t) * 512 + hb + jj] = h;
    }
}

// ---------------- score: out[b][t][m] = sum_h tanh(feat+q) * v --------------
// 128 threads, warp -> TWO m rows (shares each loaded q row across both).

__global__ __launch_bounds__(128) void score_kernel(const float* __restrict__ v,
                                                    float* __restrict__ out) {
    cudaGridDependencySynchronize();
    const int b  = blockIdx.y, mg = blockIdx.x;       // mg 0..31
    const int w  = threadIdx.x >> 5, lane = threadIdx.x & 31;
    const int m0 = mg * 8 + w * 2;                    // warp's two m rows
    const float* fp0 = g_feat + (size_t)((b << 8) + m0) * 512;
    const float* fp1 = fp0 + 512;

    float4 ff0[4], ff1[4], vv[4];
#pragma unroll
    for (int j = 0; j < 4; j++) {
        ff0[j] = *(const float4*)&fp0[lane * 4 + j * 128];
        ff1[j] = *(const float4*)&fp1[lane * 4 + j * 128];
        vv[j]  = *(const float4*)&v[lane * 4 + j * 128];
    }
    for (int t = 0; t < 64; t++) {
        const float* qp = g_q + (size_t)((b << 6) + t) * 512;
        float s0 = 0.0f, s1 = 0.0f;
#pragma unroll
        for (int j = 0; j < 4; j++) {
            float4 qv = __ldg((const float4*)&qp[lane * 4 + j * 128]);
            s0 += tanh_fast(ff0[j].x + qv.x) * vv[j].x;
            s0 += tanh_fast(ff0[j].y + qv.y) * vv[j].y;
            s0 += tanh_fast(ff0[j].z + qv.z) * vv[j].z;
            s0 += tanh_fast(ff0[j].w + qv.w) * vv[j].w;
            s1 += tanh_fast(ff1[j].x + qv.x) * vv[j].x;
            s1 += tanh_fast(ff1[j].y + qv.y) * vv[j].y;
            s1 += tanh_fast(ff1[j].z + qv.z) * vv[j].z;
            s1 += tanh_fast(ff1[j].w + qv.w) * vv[j].w;
        }
#pragma unroll
        for (int off = 16; off; off >>= 1) {
            s0 += __shfl_xor_sync(0xffffffffu, s0, off);
            s1 += __shfl_xor_sync(0xffffffffu, s1, off);
        }
        if (lane == 0) {
            float* orow = out + (size_t)((b << 6) + t) * 256;
            orow[m0]     = s0;
            orow[m0 + 1] = s1;
        }
    }
}

// ---------------- PDL launch helper -----------------------------------------

template <typename F, typename... Args>
static inline void launch_pdl(F f, dim3 grid, dim3 block, size_t smem, Args... args) {
    cudaLaunchConfig_t cfg = {};
    cfg.gridDim = grid;
    cfg.blockDim = block;
    cfg.dynamicSmemBytes = smem;
    cfg.stream = 0;
    cudaLaunchAttribute attr[1];
    attr[0].id = cudaLaunchAttributeProgrammaticStreamSerialization;
    attr[0].val.programmaticStreamSerializationAllowed = 1;
    cfg.attrs = attr;
    cfg.numAttrs = 1;
    cudaLaunchKernelEx(&cfg, f, args...);
}

// ---------------- launch ----------------------------------------------------

extern "C" void kernel_launch(void* const* d_in, const int* in_sizes, int n_in,
                              void* d_out, int out_size) {
    const int o = (n_in == 12) ? 1 : 0;
    const float* ks      = (const float*)d_in[0];
    const float* lstm_in = (const float*)d_in[2 - o];
    const float* init_h  = (const float*)d_in[3 - o];
    const float* init_c  = (const float*)d_in[4 - o];
    const float* init_i  = (const float*)d_in[5 - o];
    const float* w_ih    = (const float*)d_in[6 - o];
    const float* w_hh    = (const float*)d_in[7 - o];
    const float* b_ih    = (const float*)d_in[8 - o];
    const float* b_hh    = (const float*)d_in[9 - o];
    const float* attn_wm = (const float*)d_in[10 - o];
    const float* attn_wq = (const float*)d_in[11 - o];
    const float* attn_v  = (const float*)d_in[12 - o];
    float* out = (float*)d_out;

    void *p_xcat, *p_wihT, *p_xg, *p_feat, *p_ys, *p_q;
    cudaGetSymbolAddress(&p_xcat, g_xcat);
    cudaGetSymbolAddress(&p_wihT, g_wihT);
    cudaGetSymbolAddress(&p_xg,   g_xg);
    cudaGetSymbolAddress(&p_feat, g_feat);
    cudaGetSymbolAddress(&p_ys,   g_ys);
    cudaGetSymbolAddress(&p_q,    g_q);

    const size_t lstm_smem = 2 * 16 * 516 * sizeof(float);   // 66048 B
    cudaFuncSetAttribute(lstm_step_kernel,
                         cudaFuncAttributeMaxDynamicSharedMemorySize,
                         (int)lstm_smem);

    // 1) prep
    pack_x_kernel<<<512, 256>>>(lstm_in, init_i);
    transpose_kernel<<<dim3(512 / 32, 2048 / 32), 256>>>(w_ih);
    init_hc_kernel<<<32, 256>>>(init_h, init_c);

    // 2+3) merged: xg = x @ w_ihT  AND  feat = ks @ attn_wm (one launch)
    launch_pdl(gemm_merged_kernel, dim3(512), dim3(128), 0,
               (const float*)p_xcat, (const float*)p_wihT, (float*)p_xg,
               ks, attn_wm, (float*)p_feat);

    // 4) LSTM: 64 step launches (exact R12 kernel)
    for (int t = 0; t < 64; t++)
        launch_pdl(lstm_step_kernel, dim3(128), dim3(256), lstm_smem,
                   t, w_hh, b_ih, b_hh);

    // 5) q = ys @ attn_wq  [1024 x 512]
    launch_pdl(gemm_single_kernel, dim3(512 / 64, 1024 / 128), dim3(128), 0,
               (const float*)p_ys, attn_wq, (float*)p_q, 512, 512);

    // 6) score (2 m per warp)
    launch_pdl(score_kernel, dim3(32, 16), dim3(128), 0, attn_v, out);
}

// round 16
// speedup vs baseline: 1.8093x; 1.0899x over previous
#include <cuda_runtime.h>
#include <cuda_bf16.h>
#include <cstdint>

// ---------------------------------------------------------------------------
// LSTMPointerNet: BS=16, NMEM=256, NQ=63 (T=64), D=512, H=512
// Output: score [16,64,256] f32
//
// R16: R15 skeleton (validated 571.5us) + two additive changes:
//  (a) score uses tanh.approx.f32 (1 MUFU vs 2) -> score ~64us -> ~32us;
//      accuracy cost ~2-4e-4 l2-relative (unamplified stage), under 1e-3.
//  (b) pack/transpose/init fused into one prep kernel (saves launch gaps).
// LSTM step kernel and GEMMs byte-identical to R15.
// ---------------------------------------------------------------------------

__device__ float g_xcat[1024 * 512];    // [t*16+b][d]
__device__ float g_wihT[512 * 2048];    // w_ih^T  [d][4H]
__device__ float g_xg  [1024 * 2048];   // [t*16+b][4H]  x @ w_ih^T (no bias)
__device__ float g_feat[4096 * 512];    // [b*256+m][h]
__device__ float g_ys  [1024 * 512];    // [b*64+t][h]
__device__ float g_q   [1024 * 512];    // [b*64+t][h]
__device__ float g_h   [2 * 512 * 16];  // double-buffered h, [buf][k][b]
__device__ float g_c   [512 * 16];      // cell state, [k][b]

// ---------------- helpers ---------------------------------------------------

__device__ __forceinline__ void fma2(unsigned long long& d,
                                     unsigned long long a,
                                     unsigned long long b) {
    asm("fma.rn.f32x2 %0, %1, %2, %0;" : "+l"(d) : "l"(a), "l"(b));
}
__device__ __forceinline__ unsigned long long pk2(float x) {
    unsigned long long r;
    asm("mov.b64 %0, {%1, %1};" : "=l"(r) : "f"(x));
    return r;
}
__device__ __forceinline__ void unpk(unsigned long long v, float& lo, float& hi) {
    asm("mov.b64 {%0, %1}, %2;" : "=f"(lo), "=f"(hi) : "l"(v));
}
__device__ __forceinline__ float upsum(unsigned long long v) {
    float lo, hi; unpk(v, lo, hi); return lo + hi;
}
__device__ __forceinline__ float4 ldcg4(const float* p) {
    float4 v;
    asm volatile("ld.global.cg.v4.f32 {%0,%1,%2,%3}, [%4];"
                 : "=f"(v.x), "=f"(v.y), "=f"(v.z), "=f"(v.w) : "l"(p));
    return v;
}
__device__ __forceinline__ float rcp_approx(float x) {
    float r;
    asm("rcp.approx.f32 %0, %1;" : "=f"(r) : "f"(x));
    return r;
}

// hw tanh: 1 MUFU, rel err ~2^-11 (score stage only -- unamplified)
__device__ __forceinline__ float tanh_hw(float x) {
    float r;
    asm("tanh.approx.f32 %0, %1;" : "=f"(r) : "f"(x));
    return r;
}

// rational poly tanh (cell tail only; R12-validated)
__device__ __forceinline__ float tanh_poly(float x) {
    const float kClamp = 7.90531110763549805f;
    float xc = fminf(fmaxf(x, -kClamp), kClamp);
    float x2 = xc * xc;
    float p = fmaf(x2, -2.76076847742355e-16f, 2.00018790482477e-13f);
    p = fmaf(x2, p, -8.60467152213735e-11f);
    p = fmaf(x2, p, 5.12229709037114e-08f);
    p = fmaf(x2, p, 1.48572235717979e-05f);
    p = fmaf(x2, p, 6.37261928875436e-04f);
    p = fmaf(x2, p, 4.89352455891786e-03f);
    p *= xc;
    float q = fmaf(x2, 1.19825839466702e-06f, 1.18534705686654e-04f);
    q = fmaf(x2, q, 2.26843463243900e-03f);
    q = fmaf(x2, q, 4.89352518554385e-03f);
    return p * rcp_approx(q);
}
__device__ __forceinline__ float sigm_poly(float x) {
    return fmaf(0.5f, tanh_poly(0.5f * x), 0.5f);
}

// ---------------- fused prep: pack x, transpose w_ih, init h/c ---------------
// blocks 0..511: pack; 512..1535: transpose; 1536..1567: init.

__global__ __launch_bounds__(256) void prep_kernel(const float* __restrict__ lstm_in,
                                                   const float* __restrict__ init_i,
                                                   const float* __restrict__ w_ih,
                                                   const float* __restrict__ init_h,
                                                   const float* __restrict__ init_c) {
    __shared__ float tile[32][33];
    const int bid = blockIdx.x;
    const int tid = threadIdx.x;
    if (bid < 512) {
        // pack x = concat(init_i, lstm_in), seq-first
        int gid  = bid * 256 + tid;      // 131072 float4s
        int fidx = gid * 4;
        int row  = fidx >> 9;            // t*16 + b
        int d    = fidx & 511;
        int t = row >> 4, b = row & 15;
        float4 v;
        if (t == 0) v = *(const float4*)&init_i[d];
        else        v = *(const float4*)&lstm_in[(size_t)(b * 63 + (t - 1)) * 512 + d];
        *(float4*)&g_xcat[fidx] = v;
    } else if (bid < 1536) {
        // transpose w_ih [2048,512] -> g_wihT [512,2048]
        int id = bid - 512;
        int cb = (id & 15) * 32;         // col base in w_ih (0..511)
        int rb = (id >> 4) * 32;         // row base in w_ih (0..2047)
        int tx = tid & 31, ty = tid >> 5;
#pragma unroll
        for (int i = 0; i < 4; i++)
            tile[ty + i * 8][tx] = w_ih[(size_t)(rb + ty + i * 8) * 512 + cb + tx];
        __syncthreads();
#pragma unroll
        for (int i = 0; i < 4; i++)
            g_wihT[(size_t)(cb + ty + i * 8) * 2048 + rb + tx] = tile[tx][ty + i * 8];
    } else {
        // init h ([k][b]) and c ([k][b])
        int gid = (bid - 1536) * 256 + tid;   // 8192 entries
        int k = gid >> 4, b = gid & 15;
        g_h[k * 16 + b] = init_h[k];
        g_c[k * 16 + b] = init_c[k];
    }
}

// ---------------- f32x2 GEMM body (register double-buffered) -----------------
// C[M,N] = A[M,K] @ B[K,N]. 128 threads, tile 128x64, 8x8/thread.

__device__ __forceinline__ void gemm_body(const float* __restrict__ A,
                                          const float* __restrict__ B,
                                          float* __restrict__ C,
                                          int N, int K, int m0, int n0,
                                          float (*As)[132], float (*Bs)[64]) {
    const int tid = threadIdx.x;
    const int tx = tid & 7;
    const int ty = tid >> 3;

    unsigned long long acc[8][4];
#pragma unroll
    for (int i = 0; i < 8; i++)
#pragma unroll
        for (int p = 0; p < 4; p++) acc[i][p] = 0ull;

    float4 ra[4], rb[2];
#pragma unroll
    for (int l = 0; l < 4; l++) {
        int e = tid + l * 128;
        int row = e >> 2, kq = e & 3;
        ra[l] = *(const float4*)&A[(size_t)(m0 + row) * K + kq * 4];
    }
#pragma unroll
    for (int l = 0; l < 2; l++) {
        int e = tid + l * 128;
        int kr = e >> 4, nq = e & 15;
        rb[l] = *(const float4*)&B[(size_t)kr * N + n0 + nq * 4];
    }

    for (int k0 = 0; k0 < K; k0 += 16) {
#pragma unroll
        for (int l = 0; l < 4; l++) {
            int e = tid + l * 128;
            int row = e >> 2, kq = e & 3;
            As[kq * 4 + 0][row] = ra[l].x;
            As[kq * 4 + 1][row] = ra[l].y;
            As[kq * 4 + 2][row] = ra[l].z;
            As[kq * 4 + 3][row] = ra[l].w;
        }
#pragma unroll
        for (int l = 0; l < 2; l++) {
            int e = tid + l * 128;
            int kr = e >> 4, nq = e & 15;
            *(float4*)&Bs[kr][nq * 4] = rb[l];
        }
        __syncthreads();
        if (k0 + 16 < K) {
#pragma unroll
            for (int l = 0; l < 4; l++) {
                int e = tid + l * 128;
                int row = e >> 2, kq = e & 3;
                ra[l] = *(const float4*)&A[(size_t)(m0 + row) * K + k0 + 16 + kq * 4];
            }
#pragma unroll
            for (int l = 0; l < 2; l++) {
                int e = tid + l * 128;
                int kr = e >> 4, nq = e & 15;
                rb[l] = *(const float4*)&B[(size_t)(k0 + 16 + kr) * N + n0 + nq * 4];
            }
        }
#pragma unroll
        for (int k = 0; k < 16; k++) {
            float4 a0 = *(const float4*)&As[k][ty * 8];
            float4 a1 = *(const float4*)&As[k][ty * 8 + 4];
            ulonglong2 blo = *(const ulonglong2*)&Bs[k][tx * 4];
            ulonglong2 bhi = *(const ulonglong2*)&Bs[k][32 + tx * 4];
            float am[8] = {a0.x, a0.y, a0.z, a0.w, a1.x, a1.y, a1.z, a1.w};
#pragma unroll
            for (int i = 0; i < 8; i++) {
                unsigned long long pa = pk2(am[i]);
                fma2(acc[i][0], pa, blo.x);
                fma2(acc[i][1], pa, blo.y);
                fma2(acc[i][2], pa, bhi.x);
                fma2(acc[i][3], pa, bhi.y);
            }
        }
        __syncthreads();
    }
#pragma unroll
    for (int i = 0; i < 8; i++) {
        float* crow = C + (size_t)(m0 + ty * 8 + i) * N;
#pragma unroll
        for (int g = 0; g < 2; g++) {
#pragma unroll
            for (int p = 0; p < 2; p++) {
                int n = n0 + g * 32 + tx * 4 + p * 2;
                float lo, hi;
                unpk(acc[i][g * 2 + p], lo, hi);
                crow[n]     = lo;
                crow[n + 1] = hi;
            }
        }
    }
}

// merged launch: blocks 0..255 -> xg (1024x2048x512), 256..511 -> feat
// (4096x512x512).
__global__ __launch_bounds__(128) void gemm_merged_kernel(const float* __restrict__ xcat,
                                                          const float* __restrict__ wihT,
                                                          float* __restrict__ xg,
                                                          const float* __restrict__ ks,
                                                          const float* __restrict__ wm,
                                                          float* __restrict__ feat) {
    __shared__ float As[16][132];
    __shared__ float Bs[16][64];
    cudaGridDependencySynchronize();
    const int bid = blockIdx.x;
    if (bid < 256) {
        int bx = bid & 31, by = bid >> 5;     // nx=32, ny=8
        gemm_body(xcat, wihT, xg, 2048, 512, by * 128, bx * 64, As, Bs);
    } else {
        int id = bid - 256;
        int bx = id & 7, by = id >> 3;        // nx=8, ny=32
        gemm_body(ks, wm, feat, 512, 512, by * 128, bx * 64, As, Bs);
    }
    cudaTriggerProgrammaticLaunchCompletion();
}

// single-problem GEMM (q = ys @ wq)
__global__ __launch_bounds__(128) void gemm_single_kernel(const float* __restrict__ A,
                                                          const float* __restrict__ B,
                                                          float* __restrict__ C,
                                                          int N, int K) {
    __shared__ float As[16][132];
    __shared__ float Bs[16][64];
    cudaGridDependencySynchronize();
    gemm_body(A, B, C, N, K, blockIdx.y * 128, blockIdx.x * 64, As, Bs);
    cudaTriggerProgrammaticLaunchCompletion();
}

// ---------------- LSTM single step (exact R12/R15 kernel) --------------------

extern __shared__ float s_dyn[];   // [0:16*516) hs | [16*516:2*16*516) ws

__global__ __launch_bounds__(256) void lstm_step_kernel(int t,
                                                        const float* __restrict__ w_hh,
                                                        const float* __restrict__ b_ih,
                                                        const float* __restrict__ b_hh) {
    __shared__ float gsm[16][17];   // [local gate row][b]
    float* hs = s_dyn;              // [b][k], stride 516
    float* ws = s_dyn + 16 * 516;   // [r][k], stride 516

    const int tid = threadIdx.x;
    const int hb  = blockIdx.x * 4;
    const int b   = tid & 15;
    const int r   = tid >> 4;                    // 0..15
    const int grow = (r >> 2) * 512 + hb + (r & 3);

    const float xg = g_xg[t * 32768 + b * 2048 + grow];
    const float bs = b_ih[grow] + b_hh[grow];
    int widx[8], wrow[8];
#pragma unroll
    for (int i = 0; i < 8; i++) {
        int e = tid + i * 256;          // 0..2047 float4s
        wrow[i] = e >> 7;               // local row 0..15
        widx[i] = e & 127;              // float4 within row
    }

    cudaGridDependencySynchronize();

    const float* hp = g_h + (t & 1) * 8192;
#pragma unroll
    for (int i = 0; i < 8; i++) {
        int idx = tid + i * 256;        // 2048 float4s
        int k = idx >> 2, bq = (idx & 3) * 4;
        float4 v = ldcg4(hp + idx * 4);
        hs[(bq + 0) * 516 + k] = v.x;
        hs[(bq + 1) * 516 + k] = v.y;
        hs[(bq + 2) * 516 + k] = v.z;
        hs[(bq + 3) * 516 + k] = v.w;
    }
#pragma unroll
    for (int i = 0; i < 8; i++) {
        int lr = wrow[i];
        int gr = (lr >> 2) * 512 + hb + (lr & 3);
        float4 v = ldcg4(&w_hh[(size_t)gr * 512 + widx[i] * 4]);
        *(float4*)&ws[lr * 516 + widx[i] * 4] = v;
    }
    __syncthreads();

    cudaTriggerProgrammaticLaunchCompletion();

    const float* hrow = hs + b * 516;
    const float* wrw  = ws + r * 516;
    unsigned long long a0 = 0, a1 = 0, a2 = 0, a3 = 0;
#pragma unroll 8
    for (int k = 0; k < 512; k += 8) {
        ulonglong2 h0 = *(const ulonglong2*)(hrow + k);
        ulonglong2 h1 = *(const ulonglong2*)(hrow + k + 4);
        ulonglong2 w0 = *(const ulonglong2*)(wrw + k);
        ulonglong2 w1 = *(const ulonglong2*)(wrw + k + 4);
        fma2(a0, h0.x, w0.x);
        fma2(a1, h0.y, w0.y);
        fma2(a2, h1.x, w1.x);
        fma2(a3, h1.y, w1.y);
    }
    gsm[r][b] = (xg + (upsum(a0) + upsum(a1) + upsum(a2) + upsum(a3))) + bs;
    __syncthreads();

    if (tid < 64) {
        int jj = tid >> 4, bb = tid & 15;
        float gi = sigm_poly(gsm[jj][bb]);        // gate i
        float gf = sigm_poly(gsm[4 + jj][bb]);    // gate f
        float gg = tanh_poly(gsm[8 + jj][bb]);    // gate g
        float go = sigm_poly(gsm[12 + jj][bb]);   // gate o
        int ci = (hb + jj) * 16 + bb;
        float c = gf * g_c[ci] + gi * gg;
        g_c[ci] = c;
        float h = go * tanh_poly(c);
        g_h[((t + 1) & 1) * 8192 + ci] = h;
        g_ys[(size_t)((bb << 6) + t) * 512 + hb + jj] = h;
    }
}

// ---------------- score: out[b][t][m] = sum_h tanh(feat+q) * v --------------
// 128 threads, warp -> TWO m rows; tanh.approx (1 MUFU).

__global__ __launch_bounds__(128) void score_kernel(const float* __restrict__ v,
                                                    float* __restrict__ out) {
    cudaGridDependencySynchronize();
    const int b  = blockIdx.y, mg = blockIdx.x;       // mg 0..31
    const int w  = threadIdx.x >> 5, lane = threadIdx.x & 31;
    const int m0 = mg * 8 + w * 2;
    const float* fp0 = g_feat + (size_t)((b << 8) + m0) * 512;
    const float* fp1 = fp0 + 512;

    float4 ff0[4], ff1[4], vv[4];
#pragma unroll
    for (int j = 0; j < 4; j++) {
        ff0[j] = *(const float4*)&fp0[lane * 4 + j * 128];
        ff1[j] = *(const float4*)&fp1[lane * 4 + j * 128];
        vv[j]  = *(const float4*)&v[lane * 4 + j * 128];
    }
    for (int t = 0; t < 64; t++) {
        const float* qp = g_q + (size_t)((b << 6) + t) * 512;
        float s0 = 0.0f, s1 = 0.0f;
#pragma unroll
        for (int j = 0; j < 4; j++) {
            float4 qv = __ldg((const float4*)&qp[lane * 4 + j * 128]);
            s0 += tanh_hw(ff0[j].x + qv.x) * vv[j].x;
            s0 += tanh_hw(ff0[j].y + qv.y) * vv[j].y;
            s0 += tanh_hw(ff0[j].z + qv.z) * vv[j].z;
            s0 += tanh_hw(ff0[j].w + qv.w) * vv[j].w;
            s1 += tanh_hw(ff1[j].x + qv.x) * vv[j].x;
            s1 += tanh_hw(ff1[j].y + qv.y) * vv[j].y;
            s1 += tanh_hw(ff1[j].z + qv.z) * vv[j].z;
            s1 += tanh_hw(ff1[j].w + qv.w) * vv[j].w;
        }
#pragma unroll
        for (int off = 16; off; off >>= 1) {
            s0 += __shfl_xor_sync(0xffffffffu, s0, off);
            s1 += __shfl_xor_sync(0xffffffffu, s1, off);
        }
        if (lane == 0) {
            float* orow = out + (size_t)((b << 6) + t) * 256;
            orow[m0]     = s0;
            orow[m0 + 1] = s1;
        }
    }
}

// ---------------- PDL launch helper -----------------------------------------

template <typename F, typename... Args>
static inline void launch_pdl(F f, dim3 grid, dim3 block, size_t smem, Args... args) {
    cudaLaunchConfig_t cfg = {};
    cfg.gridDim = grid;
    cfg.blockDim = block;
    cfg.dynamicSmemBytes = smem;
    cfg.stream = 0;
    cudaLaunchAttribute attr[1];
    attr[0].id = cudaLaunchAttributeProgrammaticStreamSerialization;
    attr[0].val.programmaticStreamSerializationAllowed = 1;
    cfg.attrs = attr;
    cfg.numAttrs = 1;
    cudaLaunchKernelEx(&cfg, f, args...);
}

// ---------------- launch ----------------------------------------------------

extern "C" void kernel_launch(void* const* d_in, const int* in_sizes, int n_in,
                              void* d_out, int out_size) {
    const int o = (n_in == 12) ? 1 : 0;
    const float* ks      = (const float*)d_in[0];
    const float* lstm_in = (const float*)d_in[2 - o];
    const float* init_h  = (const float*)d_in[3 - o];
    const float* init_c  = (const float*)d_in[4 - o];
    const float* init_i  = (const float*)d_in[5 - o];
    const float* w_ih    = (const float*)d_in[6 - o];
    const float* w_hh    = (const float*)d_in[7 - o];
    const float* b_ih    = (const float*)d_in[8 - o];
    const float* b_hh    = (const float*)d_in[9 - o];
    const float* attn_wm = (const float*)d_in[10 - o];
    const float* attn_wq = (const float*)d_in[11 - o];
    const float* attn_v  = (const float*)d_in[12 - o];
    float* out = (float*)d_out;

    void *p_xcat, *p_wihT, *p_xg, *p_feat, *p_ys, *p_q;
    cudaGetSymbolAddress(&p_xcat, g_xcat);
    cudaGetSymbolAddress(&p_wihT, g_wihT);
    cudaGetSymbolAddress(&p_xg,   g_xg);
    cudaGetSymbolAddress(&p_feat, g_feat);
    cudaGetSymbolAddress(&p_ys,   g_ys);
    cudaGetSymbolAddress(&p_q,    g_q);

    const size_t lstm_smem = 2 * 16 * 516 * sizeof(float);   // 66048 B
    cudaFuncSetAttribute(lstm_step_kernel,
                         cudaFuncAttributeMaxDynamicSharedMemorySize,
                         (int)lstm_smem);

    // 1) fused prep (pack + transpose + init)
    prep_kernel<<<1568, 256>>>(lstm_in, init_i, w_ih, init_h, init_c);

    // 2+3) merged: xg = x @ w_ihT  AND  feat = ks @ attn_wm
    launch_pdl(gemm_merged_kernel, dim3(512), dim3(128), 0,
               (const float*)p_xcat, (const float*)p_wihT, (float*)p_xg,
               ks, attn_wm, (float*)p_feat);

    // 4) LSTM: 64 step launches
    for (int t = 0; t < 64; t++)
        launch_pdl(lstm_step_kernel, dim3(128), dim3(256), lstm_smem,
                   t, w_hh, b_ih, b_hh);

    // 5) q = ys @ attn_wq  [1024 x 512]
    launch_pdl(gemm_single_kernel, dim3(512 / 64, 1024 / 128), dim3(128), 0,
               (const float*)p_ys, attn_wq, (float*)p_q, 512, 512);

    // 6) score (2 m per warp, hw tanh)
    launch_pdl(score_kernel, dim3(32, 16), dim3(128), 0, attn_v, out);
}